// round 2
// baseline (speedup 1.0000x reference)
#include <cuda_runtime.h>
#include <cstddef>

// Problem constants (fixed shapes from setup_inputs)
#define C_    32
#define H_    192
#define W_    256
#define S_    9
#define N_    9
#define G_    8
#define CG_   4            // C/G
#define HW_   (H_*W_)      // 49152
#define HWS_  ((size_t)HW_*S_)   // 442368
#define CHWS_ ((size_t)C_*HWS_)

#define TPB 64

__device__ float g_M[C_*C_];   // Wp^T Wp
__device__ float g_v[C_];      // Wp^T bp

// ---------------- prep: M = Wp^T Wp, v = Wp^T bp ----------------
__global__ void prep_kernel(const float* __restrict__ Wp, const float* __restrict__ bp) {
    int tid = threadIdx.x;            // 1024 threads
    int i = tid >> 5, j = tid & 31;
    float m = 0.f;
    #pragma unroll
    for (int d = 0; d < C_; d++) m += Wp[d*C_ + i] * Wp[d*C_ + j];
    g_M[i*C_ + j] = m;
    if (tid < C_) {
        float vv = 0.f;
        #pragma unroll
        for (int d = 0; d < C_; d++) vv += Wp[d*C_ + tid] * bp[d];
        g_v[tid] = vv;
    }
}

// ---------------- main fused kernel: one thread per pixel ----------------
__global__ void __launch_bounds__(TPB, 3)
main_kernel(const float* __restrict__ f, float* __restrict__ out) {
    extern __shared__ float wsm[];    // [(c*S+s)*TPB + tid] : att-scaled ref, conflict-free
    const int t = threadIdx.x;
    const int p = blockIdx.x * TPB + t;        // pixel index h*W+w
    const float* __restrict__ refp = f + (size_t)p * S_;   // + c*HWS_

    // ---- 1. load r_mid (s = S/2 = 4) ----
    float rm[C_];
    #pragma unroll
    for (int c = 0; c < C_; c++) rm[c] = refp[(size_t)c * HWS_ + 4];

    // ---- 2. t = M*rm + v  (M uniform across warp, float4 loads, L1-hot) ----
    float tv[C_];
    const float4* M4 = (const float4*)g_M;
    #pragma unroll
    for (int c = 0; c < C_; c++) {
        float acc = g_v[c];
        #pragma unroll
        for (int j = 0; j < C_/4; j++) {
            float4 m4 = M4[c*(C_/4) + j];
            acc += m4.x*rm[4*j] + m4.y*rm[4*j+1] + m4.z*rm[4*j+2] + m4.w*rm[4*j+3];
        }
        tv[c] = acc;
    }

    // ---- 3. logits[s] = t . r_s  ; stash ref rows to SMEM ----
    float l[S_];
    #pragma unroll
    for (int s = 0; s < S_; s++) l[s] = 0.f;
    #pragma unroll 4
    for (int c = 0; c < C_; c++) {
        const float* rp = refp + (size_t)c * HWS_;
        float r[S_];
        #pragma unroll
        for (int s = 0; s < S_; s++) r[s] = rp[s];
        #pragma unroll
        for (int s = 0; s < S_; s++) {
            l[s] += tv[c] * r[s];
            wsm[(c*S_ + s)*TPB + t] = r[s];
        }
    }

    // ---- 4. softmax over s (shift-invariant terms dropped) ----
    const float inv_sqrtC = 0.17677669529663687f;  // 1/sqrt(32)
    float mx = l[0];
    #pragma unroll
    for (int s = 1; s < S_; s++) mx = fmaxf(mx, l[s]);
    float att[S_], sum = 0.f;
    #pragma unroll
    for (int s = 0; s < S_; s++) { att[s] = __expf((l[s] - mx) * inv_sqrtC); sum += att[s]; }
    float isum = __frcp_rn(sum);
    #pragma unroll
    for (int s = 0; s < S_; s++) att[s] *= isum;

    // ---- 5. rescale stash: w[c][s] = ref[c][s] * att[s] ----
    #pragma unroll 4
    for (int c = 0; c < C_; c++) {
        #pragma unroll
        for (int s = 0; s < S_; s++)
            wsm[(c*S_ + s)*TPB + t] *= att[s];
    }

    // ---- 6. stream sources: out[n][g] = sum_{c in g, s} w[c][s]*src[n][c][s] ----
    #pragma unroll 1
    for (int g = 0; g < G_; g++) {
        float acc[8];
        #pragma unroll
        for (int n = 0; n < 8; n++) acc[n] = 0.f;
        #pragma unroll 1
        for (int cc = 0; cc < CG_; cc++) {
            const int c = g*CG_ + cc;
            float w9[S_];
            #pragma unroll
            for (int s = 0; s < S_; s++) w9[s] = wsm[(c*S_ + s)*TPB + t];
            #pragma unroll
            for (int n = 0; n < 8; n++) {
                const float* __restrict__ sp =
                    f + (size_t)(n+1)*CHWS_ + (size_t)c*HWS_ + (size_t)p*S_;
                #pragma unroll
                for (int s = 0; s < S_; s++) acc[n] += w9[s] * sp[s];
            }
        }
        #pragma unroll
        for (int n = 0; n < 8; n++)
            out[(size_t)(n*G_ + g)*HW_ + p] = acc[n];
    }
}

extern "C" void kernel_launch(void* const* d_in, const int* in_sizes, int n_in,
                              void* d_out, int out_size) {
    // Identify inputs by element count (robust to metadata ordering):
    //   f: 9*32*192*256*9 = 127401984, Wp: 1024, bp: 32, (o,G scalars ignored)
    const float* f  = nullptr;
    const float* Wp = nullptr;
    const float* bp = nullptr;
    for (int i = 0; i < n_in; i++) {
        if      (in_sizes[i] == 127401984) f  = (const float*)d_in[i];
        else if (in_sizes[i] == 1024)      Wp = (const float*)d_in[i];
        else if (in_sizes[i] == 32)        bp = (const float*)d_in[i];
    }
    if (!f || !Wp || !bp) {  // fallback to positional order: f, Wp, bp
        f  = (const float*)d_in[0];
        Wp = (const float*)d_in[1];
        bp = (const float*)d_in[2];
    }
    float* out = (float*)d_out;

    const int smem = C_*S_*TPB*(int)sizeof(float);   // 73728 B
    cudaFuncSetAttribute(main_kernel, cudaFuncAttributeMaxDynamicSharedMemorySize, smem);

    prep_kernel<<<1, 1024>>>(Wp, bp);
    main_kernel<<<HW_/TPB, TPB, smem>>>(f, out);
}